// round 2
// baseline (speedup 1.0000x reference)
#include <cuda_runtime.h>
#include <cuda_fp16.h>
#include <cstdint>
#include <cstddef>

// Problem dims
#define L_DIM 1024
#define B_DIM 32
#define D_DIM 1024
#define M_DIM (L_DIM * B_DIM)     // 32768 rows (l*B+b)
#define N_DIM 3072                // 3*D output cols (planar-permuted)
#define KA    2048                // A storage: [xh(1024) | xl(1024)] fp16
#define NKT   32                  // K' = 2048 = 32 tiles of 64
#define STRIDE_P (B_DIM * D_DIM)  // 32768

// ---------------- device scratch (static: no allocs allowed) ----------------
__device__ __half g_A[(size_t)M_DIM * KA];           // 128 MB: x hi/lo fp16, (M, 2048)
__device__ __half g_Bm[(size_t)N_DIM * D_DIM];       // 6 MB: permuted W^T fp16, (N, 1024)
__device__ float g_u0[(size_t)M_DIM * D_DIM];        // 128 MB
__device__ float g_g1[(size_t)M_DIM * D_DIM];        // 128 MB (post-sigmoid)
__device__ float g_g2[(size_t)M_DIM * D_DIM];        // 128 MB (post-sigmoid)

// ---------------- ptx helpers (sm_100 baseline ISA only) ----------------
__device__ __forceinline__ uint32_t smem_u32(const void* p) {
    uint32_t a;
    asm("{ .reg .u64 t; cvta.to.shared.u64 t, %1; cvt.u32.u64 %0, t; }" : "=r"(a) : "l"(p));
    return a;
}
__device__ __forceinline__ void cp16(uint32_t dst, const void* src) {
    asm volatile("cp.async.cg.shared.global [%0], [%1], 16;" :: "r"(dst), "l"(src));
}
__device__ __forceinline__ void cp_commit() { asm volatile("cp.async.commit_group;"); }
__device__ __forceinline__ void cp_wait1()  { asm volatile("cp.async.wait_group 1;"); }
__device__ __forceinline__ void cp_wait0()  { asm volatile("cp.async.wait_group 0;"); }

__device__ __forceinline__ void ldsm4(uint32_t* r, uint32_t addr) {
    asm volatile("ldmatrix.sync.aligned.m8n8.x4.shared.b16 {%0,%1,%2,%3}, [%4];"
                 : "=r"(r[0]), "=r"(r[1]), "=r"(r[2]), "=r"(r[3]) : "r"(addr));
}
__device__ __forceinline__ void mma16816(float* d, const uint32_t* a, const uint32_t* b) {
    asm volatile(
        "mma.sync.aligned.m16n8k16.row.col.f32.f16.f16.f32 "
        "{%0,%1,%2,%3}, {%4,%5,%6,%7}, {%8,%9}, {%0,%1,%2,%3};"
        : "+f"(d[0]), "+f"(d[1]), "+f"(d[2]), "+f"(d[3])
        : "r"(a[0]), "r"(a[1]), "r"(a[2]), "r"(a[3]), "r"(b[0]), "r"(b[1]));
}

// ---------------- conversion kernels ----------------
__global__ void conv_x_kernel(const float* __restrict__ x) {
    int idx = blockIdx.x * blockDim.x + threadIdx.x;      // < M*1024
    float v = x[idx];
    __half hi = __float2half_rn(v);
    __half lo = __float2half_rn(v - __half2float(hi));
    int m = idx >> 10, k = idx & 1023;
    size_t base = (size_t)m * KA;
    g_A[base + k] = hi;
    g_A[base + 1024 + k] = lo;
}

// W (D, 3D) interleaved -> planar-permuted transposed fp16: g_Bm[n][k]
// n in [0,3072): seg = n/1024, d = n%1024; src col = 3*d + seg
__global__ void conv_w_kernel(const float* __restrict__ W) {
    int idx = blockIdx.x * blockDim.x + threadIdx.x;      // < 3072*1024
    int n = idx >> 10, k = idx & 1023;
    int seg = n >> 10, d = n & 1023;
    g_Bm[(size_t)n * D_DIM + k] = __float2half_rn(W[(size_t)k * N_DIM + 3 * d + seg]);
}

// ---------------- GEMM: 128(M) x 256(N) tile, 512 threads, 3-stage cp.async ----------------
#define TILE_M 128
#define TILE_N 256
#define TILE_K 64
#define STAGE_BYTES (TILE_M * 128 + TILE_N * 128)   // A 16KB + B 32KB = 48KB
#define SMEM_BYTES  (3 * STAGE_BYTES)               // 144KB

__device__ __forceinline__ void load_tile(uint32_t sb, int t, int stage, int bm, int bn, int tid) {
    // K'-concat: tiles 0-15 -> xh * W, 16-31 -> xl * W
    int aoff = (t < 16) ? t * 64 : (1024 + (t - 16) * 64);
    int boff = (t & 15) * 64;
    uint32_t sA = sb + stage * STAGE_BYTES;
    uint32_t sB = sA + TILE_M * 128;
    const __half* Ag = g_A  + (size_t)(bm * TILE_M) * KA + aoff;
    const __half* Bg = g_Bm + (size_t)(bn * TILE_N) * D_DIM + boff;
    #pragma unroll
    for (int it = 0; it < 6; ++it) {
        int i = tid + it * 512;                  // 0..3071
        if (i < 1024) {
            int row = i >> 3, j = i & 7;
            cp16(sA + row * 128 + ((j ^ (row & 7)) << 4),
                 Ag + (size_t)row * KA + j * 8);
        } else {
            int li = i - 1024;
            int row = li >> 3, j = li & 7;
            cp16(sB + row * 128 + ((j ^ (row & 7)) << 4),
                 Bg + (size_t)row * D_DIM + j * 8);
        }
    }
}

__global__ void __launch_bounds__(512, 1)
gemm_kernel(const float* __restrict__ bias) {
    extern __shared__ __align__(1024) char smem[];
    uint32_t sb = smem_u32(smem);
    int tid = threadIdx.x, wid = tid >> 5, lane = tid & 31;
    int bn = blockIdx.x, bm = blockIdx.y;
    int warp_m = (wid >> 2) * 32;     // 0,32,64,96
    int warp_n = (wid & 3) * 64;      // 0,64,128,192

    float acc[2][8][4];
    #pragma unroll
    for (int mi = 0; mi < 2; ++mi)
        #pragma unroll
        for (int ni = 0; ni < 8; ++ni)
            #pragma unroll
            for (int j = 0; j < 4; ++j) acc[mi][ni][j] = 0.0f;

    // per-thread ldmatrix row/col components
    int rowA = warp_m + (lane & 15);          // + mi*16
    int kgrpA = lane >> 4;                    // 0/1 -> k chunk
    int nB = warp_n + ((lane >> 4) << 3) + (lane & 7);  // + nip*16
    int kgrpB = (lane >> 3) & 1;

    // prologue: stages 0,1
    load_tile(sb, 0, 0, bm, bn, tid); cp_commit();
    load_tile(sb, 1, 1, bm, bn, tid); cp_commit();

    for (int t = 0; t < NKT; ++t) {
        if (t < NKT - 1) cp_wait1(); else cp_wait0();
        __syncthreads();
        if (t + 2 < NKT) { load_tile(sb, t + 2, (t + 2) % 3, bm, bn, tid); cp_commit(); }

        uint32_t sA = sb + (t % 3) * STAGE_BYTES;
        uint32_t sB = sA + TILE_M * 128;
        #pragma unroll
        for (int ks = 0; ks < 4; ++ks) {
            uint32_t afr[2][4];
            #pragma unroll
            for (int mi = 0; mi < 2; ++mi) {
                int r = rowA + mi * 16;
                int j = ks * 2 + kgrpA;
                ldsm4(afr[mi], sA + r * 128 + ((j ^ (r & 7)) << 4));
            }
            uint32_t bfr[4][4];
            #pragma unroll
            for (int nip = 0; nip < 4; ++nip) {
                int n = nB + nip * 16;
                int j = ks * 2 + kgrpB;
                ldsm4(bfr[nip], sB + n * 128 + ((j ^ (n & 7)) << 4));
            }
            #pragma unroll
            for (int mi = 0; mi < 2; ++mi)
                #pragma unroll
                for (int ni = 0; ni < 8; ++ni)
                    mma16816(acc[mi][ni], afr[mi], &bfr[ni >> 1][(ni & 1) * 2]);
        }
    }

    // ---------------- epilogue ----------------
    int seg = bn >> 2;                          // 256-col tile fully inside one planar segment
    int nlocbase = (bn & 3) * 256 + warp_n;     // d-coordinate base within segment
    int g = lane >> 2, tq = lane & 3;
    #pragma unroll
    for (int mi = 0; mi < 2; ++mi) {
        int r0 = bm * TILE_M + warp_m + mi * 16 + g;
        #pragma unroll
        for (int ni = 0; ni < 8; ++ni) {
            int c = nlocbase + ni * 8 + 2 * tq;
            if (seg == 0) {
                float* out = g_u0;
                *(float2*)(out + (size_t)r0 * D_DIM + c) = make_float2(acc[mi][ni][0], acc[mi][ni][1]);
                *(float2*)(out + (size_t)(r0 + 8) * D_DIM + c) = make_float2(acc[mi][ni][2], acc[mi][ni][3]);
            } else {
                const float* bp = bias + (seg - 1) * D_DIM + c;
                float b0 = bp[0], b1 = bp[1];
                float* out = (seg == 1) ? g_g1 : g_g2;
                float2 v0, v1;
                v0.x = 1.0f / (1.0f + __expf(-(acc[mi][ni][0] + b0)));
                v0.y = 1.0f / (1.0f + __expf(-(acc[mi][ni][1] + b1)));
                v1.x = 1.0f / (1.0f + __expf(-(acc[mi][ni][2] + b0)));
                v1.y = 1.0f / (1.0f + __expf(-(acc[mi][ni][3] + b1)));
                *(float2*)(out + (size_t)r0 * D_DIM + c) = v0;
                *(float2*)(out + (size_t)(r0 + 8) * D_DIM + c) = v1;
            }
        }
    }
}

// ---------------- scan: c_t = (c-u0)*g1 + u0 ; h = (tanh(c)-x)*g2 + x ----------------
__global__ void __launch_bounds__(128) scan_kernel(const float* __restrict__ x,
                                                   const float* __restrict__ c0,
                                                   float* __restrict__ h) {
    int p = blockIdx.x * 128 + threadIdx.x;   // 0..32767 (b*D+d)
    float c = c0[p];
    float u0a[4], g1a[4], g2a[4], xa[4];
    #pragma unroll
    for (int i = 0; i < 4; ++i) {
        size_t o = (size_t)i * STRIDE_P + p;
        u0a[i] = g_u0[o]; g1a[i] = g_g1[o]; g2a[i] = g_g2[o]; xa[i] = x[o];
    }
    for (int tb = 0; tb < L_DIM; tb += 4) {
        float u0b[4], g1b[4], g2b[4], xb[4];
        int nb = tb + 4;
        if (nb < L_DIM) {
            #pragma unroll
            for (int i = 0; i < 4; ++i) {
                size_t o = (size_t)(nb + i) * STRIDE_P + p;
                u0b[i] = g_u0[o]; g1b[i] = g_g1[o]; g2b[i] = g_g2[o]; xb[i] = x[o];
            }
        }
        #pragma unroll
        for (int i = 0; i < 4; ++i) {
            float u0 = u0a[i];
            c = (c - u0) * g1a[i] + u0;
            h[(size_t)(tb + i) * STRIDE_P + p] = (tanhf(c) - xa[i]) * g2a[i] + xa[i];
        }
        #pragma unroll
        for (int i = 0; i < 4; ++i) { u0a[i] = u0b[i]; g1a[i] = g1b[i]; g2a[i] = g2b[i]; xa[i] = xb[i]; }
    }
}

// ---------------- launch ----------------
extern "C" void kernel_launch(void* const* d_in, const int* in_sizes, int n_in,
                              void* d_out, int out_size) {
    const float* x    = (const float*)d_in[0];
    const float* W    = (const float*)d_in[1];
    const float* bias = (const float*)d_in[2];
    const float* c0   = (const float*)d_in[3];
    float* h = (float*)d_out;

    static int smem_set = 0;
    if (!smem_set) {
        cudaFuncSetAttribute(gemm_kernel, cudaFuncAttributeMaxDynamicSharedMemorySize, SMEM_BYTES);
        smem_set = 1;
    }

    conv_x_kernel<<<(M_DIM * D_DIM) / 256, 256>>>(x);
    conv_w_kernel<<<(N_DIM * D_DIM) / 256, 256>>>(W);
    gemm_kernel<<<dim3(N_DIM / TILE_N, M_DIM / TILE_M), 512, SMEM_BYTES>>>(bias);
    scan_kernel<<<STRIDE_P / 128, 128>>>(x, c0, h);
}

// round 3
// speedup vs baseline: 1.8236x; 1.8236x over previous
#include <cuda_runtime.h>
#include <cuda_fp16.h>
#include <cstdint>
#include <cstddef>

// Problem dims
#define L_DIM 1024
#define B_DIM 32
#define D_DIM 1024
#define M_DIM (L_DIM * B_DIM)     // 32768 rows (l*B+b)
#define N_DIM 3072                // 3*D output cols (planar-permuted)
#define KA    1024                // A storage: x fp16 (single product)
#define NKT   16                  // K' = 1024 = 16 tiles of 64
#define P_DIM (B_DIM * D_DIM)     // 32768 lanes
#define NC    16                  // scan chunks
#define LC    64                  // steps per chunk

// ---------------- device scratch (static: no allocs allowed) ----------------
__device__ __half g_A[(size_t)M_DIM * KA];           // 64 MB: x fp16, (M, 1024)
__device__ __half g_Bm[(size_t)N_DIM * D_DIM];       // 6 MB: permuted W^T fp16, (N, 1024)
__device__ float  g_u0[(size_t)M_DIM * D_DIM];       // 128 MB
__device__ __half g_g1[(size_t)M_DIM * D_DIM];       // 64 MB (post-sigmoid fp16)
__device__ __half g_g2[(size_t)M_DIM * D_DIM];       // 64 MB (post-sigmoid fp16)
__device__ float  g_cA[(size_t)NC * P_DIM];          // 2 MB chunk A
__device__ float  g_cB[(size_t)NC * P_DIM];          // 2 MB chunk B
__device__ float  g_cS[(size_t)NC * P_DIM];          // 2 MB chunk start c

// ---------------- ptx helpers (sm_100 baseline ISA only) ----------------
__device__ __forceinline__ uint32_t smem_u32(const void* p) {
    uint32_t a;
    asm("{ .reg .u64 t; cvta.to.shared.u64 t, %1; cvt.u32.u64 %0, t; }" : "=r"(a) : "l"(p));
    return a;
}
__device__ __forceinline__ void cp16(uint32_t dst, const void* src) {
    asm volatile("cp.async.cg.shared.global [%0], [%1], 16;" :: "r"(dst), "l"(src));
}
__device__ __forceinline__ void cp_commit() { asm volatile("cp.async.commit_group;"); }
__device__ __forceinline__ void cp_wait1()  { asm volatile("cp.async.wait_group 1;"); }
__device__ __forceinline__ void cp_wait0()  { asm volatile("cp.async.wait_group 0;"); }

__device__ __forceinline__ void ldsm4(uint32_t* r, uint32_t addr) {
    asm volatile("ldmatrix.sync.aligned.m8n8.x4.shared.b16 {%0,%1,%2,%3}, [%4];"
                 : "=r"(r[0]), "=r"(r[1]), "=r"(r[2]), "=r"(r[3]) : "r"(addr));
}
__device__ __forceinline__ void mma16816(float* d, const uint32_t* a, const uint32_t* b) {
    asm volatile(
        "mma.sync.aligned.m16n8k16.row.col.f32.f16.f16.f32 "
        "{%0,%1,%2,%3}, {%4,%5,%6,%7}, {%8,%9}, {%0,%1,%2,%3};"
        : "+f"(d[0]), "+f"(d[1]), "+f"(d[2]), "+f"(d[3])
        : "r"(a[0]), "r"(a[1]), "r"(a[2]), "r"(a[3]), "r"(b[0]), "r"(b[1]));
}

// ---------------- conversion kernels ----------------
__global__ void conv_x_kernel(const float* __restrict__ x) {
    int idx = blockIdx.x * blockDim.x + threadIdx.x;      // element-quad index
    float4 v = *(const float4*)(x + (size_t)idx * 4);
    __half2 h0 = __floats2half2_rn(v.x, v.y);
    __half2 h1 = __floats2half2_rn(v.z, v.w);
    *(__half2*)(g_A + (size_t)idx * 4)     = h0;
    *(__half2*)(g_A + (size_t)idx * 4 + 2) = h1;
}

// W (D, 3D) interleaved -> planar-permuted transposed fp16: g_Bm[n][k]
// n in [0,3072): seg = n/1024, d = n%1024; src col = 3*d + seg
__global__ void conv_w_kernel(const float* __restrict__ W) {
    int idx = blockIdx.x * blockDim.x + threadIdx.x;      // < 3072*1024
    int n = idx >> 10, k = idx & 1023;
    int seg = n >> 10, d = n & 1023;
    g_Bm[(size_t)n * D_DIM + k] = __float2half_rn(W[(size_t)k * N_DIM + 3 * d + seg]);
}

// ---------------- GEMM: 128(M) x 256(N) tile, 512 threads, 3-stage cp.async ----------------
#define TILE_M 128
#define TILE_N 256
#define STAGE_BYTES (TILE_M * 128 + TILE_N * 128)   // A 16KB + B 32KB = 48KB
#define SMEM_BYTES  (3 * STAGE_BYTES)               // 144KB

__device__ __forceinline__ void load_tile(uint32_t sb, int t, int stage, int bm, int bn, int tid) {
    int koff = t * 64;
    uint32_t sA = sb + stage * STAGE_BYTES;
    uint32_t sB = sA + TILE_M * 128;
    const __half* Ag = g_A  + (size_t)(bm * TILE_M) * KA + koff;
    const __half* Bg = g_Bm + (size_t)(bn * TILE_N) * D_DIM + koff;
    #pragma unroll
    for (int it = 0; it < 6; ++it) {
        int i = tid + it * 512;                  // 0..3071
        if (i < 1024) {
            int row = i >> 3, j = i & 7;
            cp16(sA + row * 128 + ((j ^ (row & 7)) << 4),
                 Ag + (size_t)row * KA + j * 8);
        } else {
            int li = i - 1024;
            int row = li >> 3, j = li & 7;
            cp16(sB + row * 128 + ((j ^ (row & 7)) << 4),
                 Bg + (size_t)row * D_DIM + j * 8);
        }
    }
}

__global__ void __launch_bounds__(512, 1)
gemm_kernel(const float* __restrict__ bias) {
    extern __shared__ __align__(1024) char smem[];
    uint32_t sb = smem_u32(smem);
    int tid = threadIdx.x, wid = tid >> 5, lane = tid & 31;
    int bn = blockIdx.x, bm = blockIdx.y;
    int warp_m = (wid >> 2) * 32;     // 0,32,64,96
    int warp_n = (wid & 3) * 64;      // 0,64,128,192

    float acc[2][8][4];
    #pragma unroll
    for (int mi = 0; mi < 2; ++mi)
        #pragma unroll
        for (int ni = 0; ni < 8; ++ni)
            #pragma unroll
            for (int j = 0; j < 4; ++j) acc[mi][ni][j] = 0.0f;

    int rowA = warp_m + (lane & 15);
    int kgrpA = lane >> 4;
    int nB = warp_n + ((lane >> 4) << 3) + (lane & 7);
    int kgrpB = (lane >> 3) & 1;

    load_tile(sb, 0, 0, bm, bn, tid); cp_commit();
    load_tile(sb, 1, 1, bm, bn, tid); cp_commit();

    for (int t = 0; t < NKT; ++t) {
        if (t < NKT - 1) cp_wait1(); else cp_wait0();
        __syncthreads();
        if (t + 2 < NKT) { load_tile(sb, t + 2, (t + 2) % 3, bm, bn, tid); cp_commit(); }

        uint32_t sA = sb + (t % 3) * STAGE_BYTES;
        uint32_t sB = sA + TILE_M * 128;
        #pragma unroll
        for (int ks = 0; ks < 4; ++ks) {
            uint32_t afr[2][4];
            #pragma unroll
            for (int mi = 0; mi < 2; ++mi) {
                int r = rowA + mi * 16;
                int j = ks * 2 + kgrpA;
                ldsm4(afr[mi], sA + r * 128 + ((j ^ (r & 7)) << 4));
            }
            uint32_t bfr[4][4];
            #pragma unroll
            for (int nip = 0; nip < 4; ++nip) {
                int n = nB + nip * 16;
                int j = ks * 2 + kgrpB;
                ldsm4(bfr[nip], sB + n * 128 + ((j ^ (n & 7)) << 4));
            }
            #pragma unroll
            for (int mi = 0; mi < 2; ++mi)
                #pragma unroll
                for (int ni = 0; ni < 8; ++ni)
                    mma16816(acc[mi][ni], afr[mi], &bfr[ni >> 1][(ni & 1) * 2]);
        }
    }

    // ---------------- epilogue ----------------
    int seg = bn >> 2;                          // 256-col tile fully inside one planar segment
    int nlocbase = (bn & 3) * 256 + warp_n;
    int g = lane >> 2, tq = lane & 3;
    #pragma unroll
    for (int mi = 0; mi < 2; ++mi) {
        int r0 = bm * TILE_M + warp_m + mi * 16 + g;
        #pragma unroll
        for (int ni = 0; ni < 8; ++ni) {
            int c = nlocbase + ni * 8 + 2 * tq;
            if (seg == 0) {
                *(float2*)(g_u0 + (size_t)r0 * D_DIM + c) = make_float2(acc[mi][ni][0], acc[mi][ni][1]);
                *(float2*)(g_u0 + (size_t)(r0 + 8) * D_DIM + c) = make_float2(acc[mi][ni][2], acc[mi][ni][3]);
            } else {
                const float* bp = bias + (seg - 1) * D_DIM + c;
                float b0 = bp[0], b1 = bp[1];
                __half* outh = (seg == 1) ? g_g1 : g_g2;
                float s0 = 1.0f / (1.0f + __expf(-(acc[mi][ni][0] + b0)));
                float s1 = 1.0f / (1.0f + __expf(-(acc[mi][ni][1] + b1)));
                float s2 = 1.0f / (1.0f + __expf(-(acc[mi][ni][2] + b0)));
                float s3 = 1.0f / (1.0f + __expf(-(acc[mi][ni][3] + b1)));
                *(__half2*)(outh + (size_t)r0 * D_DIM + c) = __floats2half2_rn(s0, s1);
                *(__half2*)(outh + (size_t)(r0 + 8) * D_DIM + c) = __floats2half2_rn(s2, s3);
            }
        }
    }
}

// ---------------- scan (chunked linear recurrence) ----------------
// c_t = g1*c_{t-1} + (1-g1)*u0  ==  (c-u0)*g1 + u0
// Pass 1: per (chunk, lane) compose A = prod g1, B = affine constant
__global__ void __launch_bounds__(256) scan_pass1() {
    int p = blockIdx.x * 256 + threadIdx.x;
    int ch = blockIdx.y;
    size_t base = (size_t)(ch * LC) * P_DIM + p;
    float A = 1.0f, Bv = 0.0f;
    #pragma unroll 4
    for (int t = 0; t < LC; ++t) {
        size_t o = base + (size_t)t * P_DIM;
        float u0 = g_u0[o];
        float g1 = __half2float(g_g1[o]);
        A *= g1;
        Bv = Bv * g1 + u0 * (1.0f - g1);
    }
    g_cA[(size_t)ch * P_DIM + p] = A;
    g_cB[(size_t)ch * P_DIM + p] = Bv;
}

// Pass 2a: chain chunk states sequentially (tiny)
__global__ void __launch_bounds__(256) scan_combine(const float* __restrict__ c0) {
    int p = blockIdx.x * 256 + threadIdx.x;
    float c = c0[p];
    #pragma unroll
    for (int ch = 0; ch < NC; ++ch) {
        size_t o = (size_t)ch * P_DIM + p;
        g_cS[o] = c;
        c = g_cA[o] * c + g_cB[o];
    }
}

// Pass 2b: apply within chunk, produce h
__global__ void __launch_bounds__(256) scan_apply(const float* __restrict__ x,
                                                  float* __restrict__ h) {
    int p = blockIdx.x * 256 + threadIdx.x;
    int ch = blockIdx.y;
    float c = g_cS[(size_t)ch * P_DIM + p];
    size_t base = (size_t)(ch * LC) * P_DIM + p;
    #pragma unroll 4
    for (int t = 0; t < LC; ++t) {
        size_t o = base + (size_t)t * P_DIM;
        float u0 = g_u0[o];
        float g1 = __half2float(g_g1[o]);
        float g2 = __half2float(g_g2[o]);
        float xv = x[o];
        c = (c - u0) * g1 + u0;
        h[o] = (tanhf(c) - xv) * g2 + xv;
    }
}

// ---------------- launch ----------------
extern "C" void kernel_launch(void* const* d_in, const int* in_sizes, int n_in,
                              void* d_out, int out_size) {
    const float* x    = (const float*)d_in[0];
    const float* W    = (const float*)d_in[1];
    const float* bias = (const float*)d_in[2];
    const float* c0   = (const float*)d_in[3];
    float* h = (float*)d_out;

    cudaFuncSetAttribute(gemm_kernel, cudaFuncAttributeMaxDynamicSharedMemorySize, SMEM_BYTES);

    conv_x_kernel<<<(M_DIM * D_DIM / 4) / 256, 256>>>(x);
    conv_w_kernel<<<(N_DIM * D_DIM) / 256, 256>>>(W);
    gemm_kernel<<<dim3(N_DIM / TILE_N, M_DIM / TILE_M), 512, SMEM_BYTES>>>(bias);
    scan_pass1<<<dim3(P_DIM / 256, NC), 256>>>();
    scan_combine<<<P_DIM / 256, 256>>>(c0);
    scan_apply<<<dim3(P_DIM / 256, NC), 256>>>(x, h);
}